// round 3
// baseline (speedup 1.0000x reference)
#include <cuda_runtime.h>

#define FULLM 0xffffffffu
#define B_N 1024
#define L_N 1024
#define T_N 21

__device__ double g_sum;
__device__ double g_cnt;

__global__ void init_k() { g_sum = 0.0; g_cnt = 0.0; }

__global__ __launch_bounds__(128) void crf_k(
    const float* __restrict__ em, const int* __restrict__ tags,
    const int* __restrict__ mask,
    const float* __restrict__ startv, const float* __restrict__ endv,
    const float* __restrict__ transv)
{
    __shared__ float tr_sm[T_N * T_N];
    int tid = threadIdx.x;
    for (int i = tid; i < T_N * T_N; i += blockDim.x) tr_sm[i] = transv[i];
    __syncthreads();

    int lane = tid & 31;
    int warp = tid >> 5;
    int b = blockIdx.x * (blockDim.x >> 5) + warp;

    bool act = lane < T_N;
    int j = act ? lane : (T_N - 1);

    // Lane j holds column j of E = exp(trans). IMP (-1e4) underflows to exactly 0.
    float Ecol[T_N];
    #pragma unroll
    for (int i = 0; i < T_N; i++) Ecol[i] = __expf(tr_sm[i * T_N + j]);

    const float* emp = em + (size_t)b * (L_N * T_N) + j;
    const int* tgp = tags + (size_t)b * L_N;
    const int* mkp = mask + (size_t)b * L_N;   // mask arrives as int32 (bool upcast)

    // t = 0
    float em0 = act ? __ldg(emp) : 0.f;
    float alpha = act ? __expf(startv[j] + em0) : 0.f;
    float logZ = 0.f;

    // tag/mask chunk prefetch (coalesced 128B, 32 steps per chunk)
    int tagch = __ldg(tgp + lane);
    int mch = __ldg(mkp + lane) ? 1 : 0;
    int tagnx = __ldg(tgp + 32 + lane);
    int mnx = __ldg(mkp + 32 + lane) ? 1 : 0;

    int tg0 = __shfl_sync(FULLM, tagch, 0);
    float score = startv[tg0] + __shfl_sync(FULLM, em0, tg0);
    int prev = tg0;
    int cnt = __shfl_sync(FULLM, mch, 0);

    // emission software pipeline, depth 8
    float embuf[8];
    #pragma unroll
    for (int k = 0; k < 8; k++) embuf[k] = act ? __ldg(emp + (1 + k) * T_N) : 0.f;

    #pragma unroll 8
    for (int t = 1; t < L_N; t++) {
        if ((t & 31) == 0) {
            tagch = tagnx; mch = mnx;
            int nt = t + 32;
            if (nt < L_N) {
                tagnx = __ldg(tgp + nt + lane);
                mnx = __ldg(mkp + nt + lane) ? 1 : 0;
            }
        }
        float cur = embuf[(t - 1) & 7];
        if (t + 8 < L_N) embuf[(t - 1) & 7] = act ? __ldg(emp + (t + 8) * T_N) : 0.f;

        float p = __expf(cur);

        // nxt_j = (sum_i alpha_i * E[i][j]) * exp(em[t][j]) -- 21 shfl + 21 FMA
        float a0 = 0.f, a1 = 0.f, a2 = 0.f;
        #pragma unroll
        for (int i = 0; i < T_N; i += 3) {
            a0 = fmaf(__shfl_sync(FULLM, alpha, i    ), Ecol[i    ], a0);
            a1 = fmaf(__shfl_sync(FULLM, alpha, i + 1), Ecol[i + 1], a1);
            a2 = fmaf(__shfl_sync(FULLM, alpha, i + 2), Ecol[i + 2], a2);
        }
        float nxt = (a0 + a1 + a2) * p;

        // numerator: trans[prev,cur] + em[t,cur], masked. em value lives in lane ct.
        int ct = __shfl_sync(FULLM, tagch, t & 31);
        int m  = __shfl_sync(FULLM, mch,  t & 31);
        float emt = __shfl_sync(FULLM, cur, ct);
        if (m) {
            score += tr_sm[prev * T_N + ct] + emt;
            cnt++;
            alpha = nxt;
        }
        prev = ct;

        // renormalize by alpha_0 every 4 steps (alpha_0 strictly > 0; growth bounded)
        if ((t & 3) == 0) {
            float d = __shfl_sync(FULLM, alpha, 0);
            alpha = __fdividef(alpha, d);
            logZ += __logf(d);
        }
    }

    // denom = logZ + log( sum_j alpha_j * exp(end_j) )
    float v = act ? alpha * __expf(endv[j]) : 0.f;
    #pragma unroll
    for (int off = 16; off > 0; off >>= 1) v += __shfl_xor_sync(FULLM, v, off);
    float denom = logZ + __logf(v);

    // end bonus at last masked tag
    int li = cnt > 0 ? cnt - 1 : 0;
    int lt = __ldg(tgp + li);
    score += endv[lt];

    if (lane == 0) {
        atomicAdd(&g_sum, (double)(score - denom));
        atomicAdd(&g_cnt, (double)cnt);
    }
}

__global__ void fin_k(float* out) { out[0] = (float)(g_sum / g_cnt); }

extern "C" void kernel_launch(void* const* d_in, const int* in_sizes, int n_in,
                              void* d_out, int out_size) {
    const float* em     = (const float*)d_in[0];
    const int* tags     = (const int*)d_in[1];
    const int* mask     = (const int*)d_in[2];
    const float* startv = (const float*)d_in[3];
    const float* endv   = (const float*)d_in[4];
    const float* trans  = (const float*)d_in[5];

    init_k<<<1, 1>>>();
    crf_k<<<B_N / 4, 128>>>(em, tags, mask, startv, endv, trans);
    fin_k<<<1, 1>>>((float*)d_out);
}